// round 13
// baseline (speedup 1.0000x reference)
#include <cuda_runtime.h>
#include <cuda_bf16.h>
#include <cstdint>

#define DD 512
#define NB 8
#define NQ 128
#define NK 256
#define MQ (NB * NQ)            // 1024 query rows
#define MTOT (MQ + NB * NK)     // 3072 total rows
#define OUTN (NB * NQ * NK)     // 262144 output elements

// ---------------------------------------------------------------------------
// Device scratch (graph-capture safe)
// ---------------------------------------------------------------------------
__device__ float g_qt[MQ * DD];               // projected queries (2 MB)
__device__ float g_kt[NB * NK * DD];          // projected keys    (4 MB)
__device__ float g_part[4][OUTN];             // D-split partial scores (4 MB)
__device__ __nv_bfloat16 g_xhi_bf[MTOT * DD]; // bf16-hi of [query;key]
__device__ __nv_bfloat16 g_xlo_bf[MTOT * DD]; // bf16-lo residual
__device__ __nv_bfloat16 g_whi_bf[1024 * DD]; // rows 0-511: W2, 512-1023: W1
__device__ __nv_bfloat16 g_wlo_bf[1024 * DD];

__device__ __forceinline__ float fast_tanh(float x) {
    float y;
    asm("tanh.approx.f32 %0, %1;" : "=f"(y) : "f"(x));
    return y;
}

__device__ __forceinline__ void bf16_split(float x, __nv_bfloat16& h, __nv_bfloat16& l) {
    h = __float2bfloat16_rn(x);
    l = __float2bfloat16_rn(x - __bfloat162float(h));
}

__device__ __forceinline__ void cp16(void* smem, const void* gmem) {
    unsigned s = (unsigned)__cvta_generic_to_shared(smem);
    asm volatile("cp.async.cg.shared.global [%0], [%1], 16;" :: "r"(s), "l"(gmem));
}
#define CP_COMMIT asm volatile("cp.async.commit_group;")
#define CP_WAIT1  asm volatile("cp.async.wait_group 1;")
#define CP_WAIT0  asm volatile("cp.async.wait_group 0;")

#define LDSM4(d0, d1, d2, d3, a)                                               \
    asm volatile("ldmatrix.sync.aligned.m8n8.x4.shared.b16 {%0,%1,%2,%3}, [%4];" \
                 : "=r"(d0), "=r"(d1), "=r"(d2), "=r"(d3) : "r"(a))
#define LDSM2(d0, d1, a)                                                       \
    asm volatile("ldmatrix.sync.aligned.m8n8.x2.shared.b16 {%0,%1}, [%2];"     \
                 : "=r"(d0), "=r"(d1) : "r"(a))

// ---------------------------------------------------------------------------
// Pad kernels: the profiled launch is always the 4th -> two pads put proj_mma
// in the ncu window this round.
// ---------------------------------------------------------------------------
__global__ void prof_pad_kernel() {}
__global__ void prof_pad_kernel2() {}

// ---------------------------------------------------------------------------
// Convert: split GEMM operands into bf16 hi/lo planes.
// ---------------------------------------------------------------------------
__global__ __launch_bounds__(256) void convert_kernel(
    const float4* __restrict__ query, const float4* __restrict__ key,
    const float4* __restrict__ W1, const float4* __restrict__ W2)
{
    const int bi = blockIdx.x;
    const float4* src;
    __nv_bfloat16 *dh, *dl;
    int base;
    if (bi < 128) {
        src = query; dh = g_xhi_bf; dl = g_xlo_bf; base = bi * 1024;
    } else if (bi < 384) {
        src = key; dh = g_xhi_bf + MQ * DD; dl = g_xlo_bf + MQ * DD;
        base = (bi - 128) * 1024;
    } else if (bi < 448) {
        src = W2; dh = g_whi_bf; dl = g_wlo_bf; base = (bi - 384) * 1024;
    } else {
        src = W1; dh = g_whi_bf + 512 * DD; dl = g_wlo_bf + 512 * DD;
        base = (bi - 448) * 1024;
    }
    float4 t[4];
#pragma unroll
    for (int i = 0; i < 4; i++)
        t[i] = src[base + threadIdx.x + i * 256];
#pragma unroll
    for (int i = 0; i < 4; i++) {
        int idx = base + threadIdx.x + i * 256;
        __nv_bfloat16 h[4], l[4];
        bf16_split(t[i].x, h[0], l[0]);
        bf16_split(t[i].y, h[1], l[1]);
        bf16_split(t[i].z, h[2], l[2]);
        bf16_split(t[i].w, h[3], l[3]);
        *(uint2*)&dh[(size_t)idx * 4] = *(uint2*)h;
        *(uint2*)&dl[(size_t)idx * 4] = *(uint2*)l;
    }
}

// ---------------------------------------------------------------------------
// Projection GEMM, bf16 m16n8k16, 3-term compensation, ldmatrix fragments.
// Tile 64x64, 128 threads, k-chunk 32, cp.async double-buffered, 384 blocks.
// (Frozen geometry: beat 128x128 and 128x64 in direct trials.)
// ---------------------------------------------------------------------------
#define BM 64
#define BN 64
#define PKC 32
#define XSTR 40

#define MMA_BF16(c, a, b0_, b1_)                                               \
    asm volatile(                                                              \
        "mma.sync.aligned.m16n8k16.row.col.f32.bf16.bf16.f32 "                 \
        "{%0,%1,%2,%3}, {%4,%5,%6,%7}, {%8,%9}, {%0,%1,%2,%3};"                \
        : "+f"((c)[0]), "+f"((c)[1]), "+f"((c)[2]), "+f"((c)[3])               \
        : "r"((a)[0]), "r"((a)[1]), "r"((a)[2]), "r"((a)[3]),                  \
          "r"(b0_), "r"(b1_))

__global__ __launch_bounds__(128) void proj_mma(
    const float* __restrict__ b1, const float* __restrict__ b2)
{
    __shared__ __nv_bfloat16 sXh[2][BM * XSTR], sXl[2][BM * XSTR];
    __shared__ __nv_bfloat16 sWh[2][BN * XSTR], sWl[2][BN * XSTR];

    const int m0 = blockIdx.x * BM;
    const int n0 = blockIdx.y * BN;
    const bool isQ = (m0 < MQ);
    const int woff = isQ ? 0 : 512 * DD;
    const __nv_bfloat16* Xhg = g_xhi_bf + (size_t)m0 * DD;
    const __nv_bfloat16* Xlg = g_xlo_bf + (size_t)m0 * DD;
    const __nv_bfloat16* Whg = g_whi_bf + woff + (size_t)n0 * DD;
    const __nv_bfloat16* Wlg = g_wlo_bf + woff + (size_t)n0 * DD;
    const float* bias = isQ ? b2 : b1;
    float* out = isQ ? (g_qt + (size_t)m0 * DD) : (g_kt + (size_t)(m0 - MQ) * DD);

    const int tid = threadIdx.x;
    const int wid = tid >> 5, lane = tid & 31;
    const int wm = (wid & 1) * 32;
    const int wn = (wid >> 1) * 32;
    const int gr = lane >> 2;
    const int gc = lane & 3;

    const int grp = lane >> 3, lr = lane & 7;
    const int a_r = (grp & 1) * 8 + lr;
    const int a_c = (grp >> 1) * 8;
    const int b_r = lr;
    const int b_c = (grp & 1) * 8;

    float acc[2][4][4];
#pragma unroll
    for (int mf = 0; mf < 2; mf++)
#pragma unroll
        for (int nf = 0; nf < 4; nf++)
#pragma unroll
            for (int j = 0; j < 4; j++) acc[mf][nf][j] = 0.0f;

    auto load_stage = [&](int st, int kc) {
        const int kb = kc * PKC;
#pragma unroll
        for (int i = 0; i < 2; i++) {
            int idx = tid + i * 128;
            int r = idx >> 2, c8 = (idx & 3) * 8;
            int so = r * XSTR + c8;
            size_t go = (size_t)r * DD + kb + c8;
            cp16(&sXh[st][so], Xhg + go);
            cp16(&sXl[st][so], Xlg + go);
            cp16(&sWh[st][so], Whg + go);
            cp16(&sWl[st][so], Wlg + go);
        }
        CP_COMMIT;
    };

    load_stage(0, 0);

    const int NCH = DD / PKC;   // 16
    for (int kc = 0; kc < NCH; kc++) {
        const int st = kc & 1;
        if (kc + 1 < NCH) {
            load_stage(st ^ 1, kc + 1);
            CP_WAIT1;
        } else {
            CP_WAIT0;
        }
        __syncthreads();

        uint32_t ah[2][2][4], al[2][2][4];
        uint32_t bh[2][4][2], bl[2][4][2];
#pragma unroll
        for (int h = 0; h < 2; h++) {
            const int k16 = h * 16;
#pragma unroll
            for (int mf = 0; mf < 2; mf++) {
                unsigned aoff = (unsigned)((wm + mf * 16 + a_r) * XSTR + k16 + a_c);
                unsigned pah = (unsigned)__cvta_generic_to_shared(&sXh[st][aoff]);
                unsigned pal = (unsigned)__cvta_generic_to_shared(&sXl[st][aoff]);
                LDSM4(ah[h][mf][0], ah[h][mf][1], ah[h][mf][2], ah[h][mf][3], pah);
                LDSM4(al[h][mf][0], al[h][mf][1], al[h][mf][2], al[h][mf][3], pal);
            }
#pragma unroll
            for (int nf = 0; nf < 4; nf++) {
                unsigned boff = (unsigned)((wn + nf * 8 + b_r) * XSTR + k16 + b_c);
                unsigned pbh = (unsigned)__cvta_generic_to_shared(&sWh[st][boff]);
                unsigned pbl = (unsigned)__cvta_generic_to_shared(&sWl[st][boff]);
                LDSM2(bh[h][nf][0], bh[h][nf][1], pbh);
                LDSM2(bl[h][nf][0], bl[h][nf][1], pbl);
            }
        }
#pragma unroll
        for (int h = 0; h < 2; h++) {
#pragma unroll
            for (int nf = 0; nf < 4; nf++) {
#pragma unroll
                for (int mf = 0; mf < 2; mf++) {
                    MMA_BF16(acc[mf][nf], ah[h][mf], bh[h][nf][0], bh[h][nf][1]);
                    MMA_BF16(acc[mf][nf], al[h][mf], bh[h][nf][0], bh[h][nf][1]);
                    MMA_BF16(acc[mf][nf], ah[h][mf], bl[h][nf][0], bl[h][nf][1]);
                }
            }
        }
        __syncthreads();
    }

    // Epilogue: + bias, f32 store
#pragma unroll
    for (int nf = 0; nf < 4; nf++) {
        int col = wn + nf * 8 + 2 * gc;
        float2 bb = *(const float2*)&bias[n0 + col];
#pragma unroll
        for (int mf = 0; mf < 2; mf++) {
            int row = wm + mf * 16 + gr;
            float2 o0, o1;
            o0.x = acc[mf][nf][0] + bb.x;  o0.y = acc[mf][nf][1] + bb.y;
            o1.x = acc[mf][nf][2] + bb.x;  o1.y = acc[mf][nf][3] + bb.y;
            *(float2*)&out[row * DD + n0 + col] = o0;
            *(float2*)&out[(row + 8) * DD + n0 + col] = o1;
        }
    }
}

// ---------------------------------------------------------------------------
// Score (D-split x4): partial[b,q,k] = sum_{d in quarter} v[d]*tanh(qt+kt)
// Tile 16q x 32k x (D/4=128), 128 threads, 2x2 micro-tile, 2048 blocks.
// NO register staging: direct LDG->STS, regs drop ~72->~56 so 9 blocks/SM
// fit; cross-block overlap (not intra-block prefetch) hides load latency.
// ---------------------------------------------------------------------------
#define SQ 16
#define SK 32
#define SD 64
#define DQUART 128

__global__ __launch_bounds__(128) void score_kernel(
    const float* __restrict__ v)
{
    __shared__ float qs[SQ][68];      // q-major
    __shared__ float ks[SD][34];      // dd-major (transposed)
    __shared__ float vs[DQUART];

    const int bz    = blockIdx.z;
    const int b     = bz >> 2;
    const int quart = bz & 3;
    const int dcb   = quart * DQUART;         // D range [dcb, dcb+128)
    const int q0 = blockIdx.y * SQ;
    const int k0 = blockIdx.x * SK;
    const float* qt = g_qt + ((size_t)b * NQ + q0) * DD;
    const float* kt = g_kt + ((size_t)b * NK + k0) * DD;
    float* po = g_part[quart];

    const int tid = threadIdx.x;
    const int tk = tid & 15;    // 2 k each
    const int tq = tid >> 4;    // 2 q each

    vs[tid] = v[dcb + tid];

    float a00 = 0.f, a01 = 0.f, a10 = 0.f, a11 = 0.f;

    for (int dl = 0; dl < DQUART; dl += SD) {
        const int dc = dcb + dl;
        // q tile: 16x64 = 256 float4, 2 per thread
#pragma unroll
        for (int i = 0; i < 2; i++) {
            int idx = tid + i * 128;
            int r = idx >> 4, c4 = (idx & 15) * 4;
            float4 t = *(const float4*)&qt[r * DD + dc + c4];
            *(float4*)&qs[r][c4] = t;
        }
        // k tile: 32x64 = 512 float4, 4 per thread, transposed to dd-major
#pragma unroll
        for (int i = 0; i < 4; i++) {
            int idx = tid + i * 128;
            int r = idx >> 4, c4 = (idx & 15) * 4;
            float4 t = *(const float4*)&kt[r * DD + dc + c4];
            ks[c4 + 0][r] = t.x;
            ks[c4 + 1][r] = t.y;
            ks[c4 + 2][r] = t.z;
            ks[c4 + 3][r] = t.w;
        }
        __syncthreads();

#pragma unroll
        for (int d4 = 0; d4 < SD; d4 += 4) {
            float4 q0v = *(const float4*)&qs[tq * 2 + 0][d4];
            float4 q1v = *(const float4*)&qs[tq * 2 + 1][d4];
            float2 kk0 = *(const float2*)&ks[d4 + 0][tk * 2];
            float2 kk1 = *(const float2*)&ks[d4 + 1][tk * 2];
            float2 kk2 = *(const float2*)&ks[d4 + 2][tk * 2];
            float2 kk3 = *(const float2*)&ks[d4 + 3][tk * 2];
            float4 vv  = *(const float4*)&vs[dl + d4];

            a00 = fmaf(vv.x, fast_tanh(q0v.x + kk0.x), a00);
            a01 = fmaf(vv.x, fast_tanh(q0v.x + kk0.y), a01);
            a10 = fmaf(vv.x, fast_tanh(q1v.x + kk0.x), a10);
            a11 = fmaf(vv.x, fast_tanh(q1v.x + kk0.y), a11);

            a00 = fmaf(vv.y, fast_tanh(q0v.y + kk1.x), a00);
            a01 = fmaf(vv.y, fast_tanh(q0v.y + kk1.y), a01);
            a10 = fmaf(vv.y, fast_tanh(q1v.y + kk1.x), a10);
            a11 = fmaf(vv.y, fast_tanh(q1v.y + kk1.y), a11);

            a00 = fmaf(vv.z, fast_tanh(q0v.z + kk2.x), a00);
            a01 = fmaf(vv.z, fast_tanh(q0v.z + kk2.y), a01);
            a10 = fmaf(vv.z, fast_tanh(q1v.z + kk2.x), a10);
            a11 = fmaf(vv.z, fast_tanh(q1v.z + kk2.y), a11);

            a00 = fmaf(vv.w, fast_tanh(q0v.w + kk3.x), a00);
            a01 = fmaf(vv.w, fast_tanh(q0v.w + kk3.y), a01);
            a10 = fmaf(vv.w, fast_tanh(q1v.w + kk3.x), a10);
            a11 = fmaf(vv.w, fast_tanh(q1v.w + kk3.y), a11);
        }
        __syncthreads();
    }

    {
        float2 o0; o0.x = a00; o0.y = a01;
        float2 o1; o1.x = a10; o1.y = a11;
        *(float2*)&po[((size_t)b * NQ + q0 + tq * 2 + 0) * NK + k0 + tk * 2] = o0;
        *(float2*)&po[((size_t)b * NQ + q0 + tq * 2 + 1) * NK + k0 + tk * 2] = o1;
    }
}

// ---------------------------------------------------------------------------
// Combine: out = part0 + part1 + part2 + part3  (65536 float4)
// ---------------------------------------------------------------------------
__global__ __launch_bounds__(256) void combine_kernel(float4* __restrict__ out)
{
    int idx = blockIdx.x * 1024 + threadIdx.x;
    const float4* p0 = (const float4*)g_part[0];
    const float4* p1 = (const float4*)g_part[1];
    const float4* p2 = (const float4*)g_part[2];
    const float4* p3 = (const float4*)g_part[3];
#pragma unroll
    for (int i = 0; i < 4; i++) {
        int j = idx + i * 256;
        float4 a = p0[j], b = p1[j], c = p2[j], d = p3[j];
        float4 o;
        o.x = (a.x + b.x) + (c.x + d.x);
        o.y = (a.y + b.y) + (c.y + d.y);
        o.z = (a.z + b.z) + (c.z + d.z);
        o.w = (a.w + b.w) + (c.w + d.w);
        out[j] = o;
    }
}

extern "C" void kernel_launch(void* const* d_in, const int* in_sizes, int n_in,
                              void* d_out, int out_size)
{
    const float* query = (const float*)d_in[0];  // [8,128,512]
    const float* key   = (const float*)d_in[1];  // [8,256,512]
    const float* W1    = (const float*)d_in[2];  // [512,512]
    const float* b1    = (const float*)d_in[3];  // [512]
    const float* W2    = (const float*)d_in[4];  // [512,512]
    const float* b2    = (const float*)d_in[5];  // [512]
    const float* v     = (const float*)d_in[6];  // [512]
    float* out = (float*)d_out;                  // [8,128,256]

    prof_pad_kernel<<<1, 32>>>();    // pads 1-2: put proj_mma (launch #4)
    prof_pad_kernel2<<<1, 32>>>();   // into the ncu profiling window
    convert_kernel<<<512, 256>>>((const float4*)query, (const float4*)key,
                                 (const float4*)W1, (const float4*)W2);
    // 48 m-tiles (3072/64) x 8 n-tiles (512/64) = 384 blocks
    proj_mma<<<dim3(48, 8), 128>>>(b1, b2);
    // 8 k-tiles x 8 q-tiles x (8 batches * 4 D-quarters) = 2048 blocks
    score_kernel<<<dim3(NK / SK, NQ / SQ, NB * 4), 128>>>(v);
    combine_kernel<<<64, 256>>>((float4*)out);
}